// round 6
// baseline (speedup 1.0000x reference)
#include <cuda_runtime.h>
#include <cuda_fp16.h>
#include <math.h>

#define N_NODES 8192
#define F_IN    512
#define HID     128
#define NCLS    16
#define CAP     160
#define KSPLIT  4

#define S1_BLOCKS 512
#define S2_BLOCKS 256

// ---------------- static scratch (no allocations allowed) ----------------
__device__ float  g_dinv[N_NODES];
__device__ int    g_cnt [N_NODES];
__device__ int    g_cols[(size_t)N_NODES * CAP];
__device__ float  g_vals[(size_t)N_NODES * CAP];
__device__ uint2  g_pack[(size_t)N_NODES * CAP];          // (col, val bits)
__device__ float  g_part[(size_t)KSPLIT * N_NODES * HID]; // split-K partials
__device__ float  g_h1  [(size_t)N_NODES * HID];          // fp32 residual h
__device__ __half g_fa  [(size_t)N_NODES * HID];          // fp16 ping
__device__ __half g_fb  [(size_t)N_NODES * HID];          // fp16 pong
__device__ float  g_relu[(size_t)N_NODES * HID];          // layer-1 output fp32
__device__ float  g_h2  [(size_t)N_NODES * NCLS];         // fp32 residual h2
__device__ __half g_ca  [(size_t)N_NODES * NCLS];         // fp16 ping (layer2)
__device__ __half g_cb  [(size_t)N_NODES * NCLS];         // fp16 pong (layer2)

__device__ int               g_bar_count;                 // zero-init
__device__ volatile unsigned g_bar_gen;                   // zero-init, monotonic

__device__ __constant__ float C_RES  = (float)(1.0 / 1.8);   // 1/(1+alpha)
__device__ __constant__ float C_PROP = (float)(0.8 / 1.8);   // alpha/(1+alpha)

// ---------------- software grid barrier (requires co-resident grid) ----------------
// __threadfence() is gpu-scope => publishes STG to L2 AND invalidates this SM's L1
// (CCTL.IVALL), so post-barrier cached global loads cannot see stale lines.
__device__ __forceinline__ void grid_barrier(int nblocks) {
    __syncthreads();
    if (threadIdx.x == 0) {
        __threadfence();                               // release + L1 invalidate
        unsigned gen = g_bar_gen;
        if (atomicAdd(&g_bar_count, 1) == nblocks - 1) {
            atomicExch(&g_bar_count, 0);
            __threadfence();
            g_bar_gen = gen + 1;
        } else {
            while (g_bar_gen == gen) { __nanosleep(32); }
        }
        __threadfence();                               // acquire + L1 invalidate
    }
    __syncthreads();
}

// ---------------- 1: single-pass build: ELL + dinv (one warp per row) ----------------
__global__ void build_kernel(const float* __restrict__ adj) {
    int warp = (blockIdx.x * blockDim.x + threadIdx.x) >> 5;
    int lane = threadIdx.x & 31;
    if (warp >= N_NODES) return;
    const int row = warp;
    const float4* rowp = (const float4*)(adj + (size_t)row * N_NODES);
    size_t base = (size_t)row * CAP;
    int cnt = 0;
    float s = 0.f;

    float4 v = __ldg(&rowp[lane]);
    for (int j0 = 0; j0 < N_NODES; j0 += 128) {
        float4 nv;
        if (j0 + 128 < N_NODES) nv = __ldg(&rowp[(j0 + 128) / 4 + lane]);
        int j = j0 + lane * 4;
        v.x += (j + 0 == row) ? 1.f : 0.f;
        v.y += (j + 1 == row) ? 1.f : 0.f;
        v.z += (j + 2 == row) ? 1.f : 0.f;
        v.w += (j + 3 == row) ? 1.f : 0.f;
        s += v.x + v.y + v.z + v.w;
        int c = (v.x != 0.f) + (v.y != 0.f) + (v.z != 0.f) + (v.w != 0.f);
        int incl = c;
#pragma unroll
        for (int d = 1; d < 32; d <<= 1) {
            int t = __shfl_up_sync(0xffffffffu, incl, d);
            if (lane >= d) incl += t;
        }
        int total = __shfl_sync(0xffffffffu, incl, 31);
        int w = cnt + incl - c;
        float vv[4] = {v.x, v.y, v.z, v.w};
#pragma unroll
        for (int q = 0; q < 4; q++) {
            if (vv[q] != 0.f) {
                if (w < CAP) { g_cols[base + w] = j + q; g_vals[base + w] = vv[q]; }
                w++;
            }
        }
        cnt += total;
        v = nv;
    }
#pragma unroll
    for (int d = 16; d; d >>= 1) s += __shfl_xor_sync(0xffffffffu, s, d);
    if (lane == 0) {
        g_cnt[row]  = (cnt < CAP) ? cnt : CAP;
        g_dinv[row] = rsqrtf(fmaxf(s, 1e-12f));       // dinv fused (degree is row-local)
    }
}

// ---------------- 2: split-K SGEMM  part[z] = A[:, zK:(z+1)K] @ B[zK:(z+1)K, :] ------
__global__ void gemm1_kernel(const float* __restrict__ A, const float* __restrict__ B) {
    const int BM = 64, BN = 64, BK = 16, KC = F_IN / KSPLIT;  // 128
    __shared__ float As[BK][BM];
    __shared__ float Bs[BK][BN];
    int m0 = blockIdx.x * BM;
    int n0 = blockIdx.y * BN;
    int kz = blockIdx.z;
    float* P = g_part + (size_t)kz * N_NODES * HID;
    int t  = threadIdx.x;
    int tx = t & 15, ty = t >> 4;
    float acc[4][4] = {};
    for (int k0 = kz * KC; k0 < kz * KC + KC; k0 += BK) {
        {
            int r = t >> 2, c4 = t & 3;
            float4 a = *(const float4*)(A + (size_t)(m0 + r) * F_IN + k0 + c4 * 4);
            As[c4 * 4 + 0][r] = a.x; As[c4 * 4 + 1][r] = a.y;
            As[c4 * 4 + 2][r] = a.z; As[c4 * 4 + 3][r] = a.w;
        }
        {
            int kr = t >> 4, c4 = t & 15;
            float4 b = *(const float4*)(B + (size_t)(k0 + kr) * HID + n0 + c4 * 4);
            Bs[kr][c4 * 4 + 0] = b.x; Bs[kr][c4 * 4 + 1] = b.y;
            Bs[kr][c4 * 4 + 2] = b.z; Bs[kr][c4 * 4 + 3] = b.w;
        }
        __syncthreads();
#pragma unroll
        for (int k = 0; k < BK; k++) {
            float av[4], bv[4];
#pragma unroll
            for (int i = 0; i < 4; i++) av[i] = As[k][ty * 4 + i];
#pragma unroll
            for (int j = 0; j < 4; j++) bv[j] = Bs[k][tx * 4 + j];
#pragma unroll
            for (int i = 0; i < 4; i++)
#pragma unroll
                for (int j = 0; j < 4; j++)
                    acc[i][j] = fmaf(av[i], bv[j], acc[i][j]);
        }
        __syncthreads();
    }
#pragma unroll
    for (int i = 0; i < 4; i++) {
        size_t off = (size_t)(m0 + ty * 4 + i) * HID + n0 + tx * 4;
        *(float4*)(P + off) = make_float4(acc[i][0], acc[i][1], acc[i][2], acc[i][3]);
    }
}

// ---------------- 3: S1 persistent: scale/pack + reduce + 8 diffusion steps + relu ----
__global__ void __launch_bounds__(256, 4) s1_kernel(const float* __restrict__ bias) {
    const int tid = blockIdx.x * 256 + threadIdx.x;      // 0 .. 131071
    const int gw   = tid >> 5;                           // global warp 0..4095
    const int lane = tid & 31;

    // --- preamble A: reduce split-K partials -> g_h1 fp32 + g_fa fp16 ---
    {
        const size_t TOT = (size_t)N_NODES * HID / 4;    // 262144 float4
        const float4* p0 = (const float4*)g_part;
        for (size_t i = tid; i < TOT; i += (size_t)S1_BLOCKS * 256) {
            float4 a = p0[i];
            float4 b = p0[TOT + i];
            float4 c = p0[2 * TOT + i];
            float4 d = p0[3 * TOT + i];
            float4 r;
            r.x = (a.x + b.x) + (c.x + d.x);
            r.y = (a.y + b.y) + (c.y + d.y);
            r.z = (a.z + b.z) + (c.z + d.z);
            r.w = (a.w + b.w) + (c.w + d.w);
            ((float4*)g_h1)[i] = r;
            __half2 h0 = __floats2half2_rn(r.x, r.y);
            __half2 h1 = __floats2half2_rn(r.z, r.w);
            ((uint2*)g_fa)[i] = make_uint2(*(unsigned*)&h0, *(unsigned*)&h1);
        }
    }
    // --- preamble B: scale vals and pack (col,val) ---
    for (int row = gw; row < N_NODES; row += 4096) {
        size_t base = (size_t)row * CAP;
        int cnt = g_cnt[row];
        float di = g_dinv[row];
        for (int e = lane; e < cnt; e += 32) {
            int c = g_cols[base + e];
            float v = g_vals[base + e] * di * __ldg(&g_dinv[c]);
            g_pack[base + e] = make_uint2((unsigned)c, __float_as_uint(v));
        }
    }
    grid_barrier(S1_BLOCKS);

    // --- 8 diffusion steps, fp16 gather / fp32 accum; last step fuses bias+relu ---
    __half* const bufs[2] = {g_fa, g_fb};
    for (int step = 0; step < 8; step++) {
        const bool fin = (step == 7);
        const uint2* __restrict__ inv = (const uint2*)bufs[step & 1];
        __half*      outh             = bufs[(step + 1) & 1];
        for (int row = gw; row < N_NODES; row += 4096) {     // exactly 2 rows/warp
            size_t base = (size_t)row * CAP;
            int cnt = g_cnt[row];
            const uint2* __restrict__ ev = g_pack + base;
            float ax = 0.f, ay = 0.f, az = 0.f, aw = 0.f;
#pragma unroll 4
            for (int e = 0; e < cnt; e++) {
                uint2 p = __ldg(&ev[e]);
                int   c = (int)p.x;
                float v = __uint_as_float(p.y);
                uint2 o = __ldg(&inv[(size_t)c * 32 + lane]);
                float2 f0 = __half22float2(*(__half2*)&o.x);
                float2 f1 = __half22float2(*(__half2*)&o.y);
                ax = fmaf(v, f0.x, ax);
                ay = fmaf(v, f0.y, ay);
                az = fmaf(v, f1.x, az);
                aw = fmaf(v, f1.y, aw);
            }
            float4 hh = ((const float4*)g_h1)[(size_t)row * 32 + lane];
            float4 r;
            r.x = C_PROP * ax + C_RES * hh.x;
            r.y = C_PROP * ay + C_RES * hh.y;
            r.z = C_PROP * az + C_RES * hh.z;
            r.w = C_PROP * aw + C_RES * hh.w;
            if (fin) {
                float4 b = ((const float4*)bias)[lane];
                r.x = fmaxf(r.x + b.x, 0.f);
                r.y = fmaxf(r.y + b.y, 0.f);
                r.z = fmaxf(r.z + b.z, 0.f);
                r.w = fmaxf(r.w + b.w, 0.f);
                ((float4*)g_relu)[(size_t)row * 32 + lane] = r;
            } else {
                __half2 h0 = __floats2half2_rn(r.x, r.y);
                __half2 h1 = __floats2half2_rn(r.z, r.w);
                ((uint2*)outh)[(size_t)row * 32 + lane] =
                    make_uint2(*(unsigned*)&h0, *(unsigned*)&h1);
            }
        }
        if (!fin) grid_barrier(S1_BLOCKS);
    }
}

// ---------------- 4: S2 persistent: gemm2 + 8 diffusion steps + log_softmax ----------
__global__ void __launch_bounds__(256, 4) s2_kernel(const float* __restrict__ W2,
                                                    const float* __restrict__ bias,
                                                    float* __restrict__ outp) {
    __shared__ float sW[HID * NCLS];                      // 8 KB
    const int t    = threadIdx.x;
    const int r    = t >> 3;                              // row-in-block 0..31
    const int l8   = t & 7;                               // 8 lanes per row
    const int row  = blockIdx.x * 32 + r;

    // --- preamble: h2 = relu_out @ W2 (fp32 residual + fp16 seed) ---
    for (int i = t; i < HID * NCLS; i += 256) sW[i] = W2[i];
    __syncthreads();
    {
        const float* Hr = g_relu + (size_t)row * HID;
        const int c = l8 * 2;
        float a0 = 0.f, a1 = 0.f;
#pragma unroll 8
        for (int k = 0; k < HID; k++) {
            float hv = __ldg(&Hr[k]);
            a0 = fmaf(hv, sW[k * NCLS + c + 0], a0);
            a1 = fmaf(hv, sW[k * NCLS + c + 1], a1);
        }
        size_t off = (size_t)row * NCLS + c;
        g_h2[off + 0] = a0;
        g_h2[off + 1] = a1;
        __half2 hv2 = __floats2half2_rn(a0, a1);
        *(unsigned*)(g_ca + off) = *(unsigned*)&hv2;
    }
    grid_barrier(S2_BLOCKS);

    // --- 8 diffusion steps, fp16 gather; final fuses bias + log_softmax -> d_out ---
    __half* const bufs[2] = {g_ca, g_cb};
    const size_t base = (size_t)row * CAP;
    const int cnt = g_cnt[row];
    for (int step = 0; step < 8; step++) {
        const bool fin = (step == 7);
        const unsigned* __restrict__ inv = (const unsigned*)bufs[step & 1];
        __half*         outh             = bufs[(step + 1) & 1];
        const uint2* __restrict__ ev = g_pack + base;
        float a0 = 0.f, a1 = 0.f;
#pragma unroll 4
        for (int e = 0; e < cnt; e++) {
            uint2 p = __ldg(&ev[e]);
            int   c = (int)p.x;
            float v = __uint_as_float(p.y);
            unsigned o = __ldg(&inv[(size_t)c * 8 + l8]);
            float2 f = __half22float2(*(__half2*)&o);
            a0 = fmaf(v, f.x, a0);
            a1 = fmaf(v, f.y, a1);
        }
        float2 hh = ((const float2*)g_h2)[(size_t)row * 8 + l8];
        float r0 = C_PROP * a0 + C_RES * hh.x;
        float r1 = C_PROP * a1 + C_RES * hh.y;
        if (fin) {
            float2 b = ((const float2*)bias)[l8];
            r0 += b.x;
            r1 += b.y;
            float m = fmaxf(r0, r1);
#pragma unroll
            for (int s = 1; s < 8; s <<= 1)
                m = fmaxf(m, __shfl_xor_sync(0xffffffffu, m, s, 8));
            float ssum = expf(r0 - m) + expf(r1 - m);
#pragma unroll
            for (int s = 1; s < 8; s <<= 1)
                ssum += __shfl_xor_sync(0xffffffffu, ssum, s, 8);
            float lse = m + logf(ssum);
            ((float2*)outp)[(size_t)row * 8 + l8] = make_float2(r0 - lse, r1 - lse);
        } else {
            __half2 hv = __floats2half2_rn(r0, r1);
            ((unsigned*)outh)[(size_t)row * 8 + l8] = *(unsigned*)&hv;
            grid_barrier(S2_BLOCKS);
        }
    }
}

// ---------------- launch: 4 kernels total ----------------
extern "C" void kernel_launch(void* const* d_in, const int* in_sizes, int n_in,
                              void* d_out, int out_size) {
    const float* x   = (const float*)d_in[0];
    const float* adj = (const float*)d_in[1];
    const float* W1  = (const float*)d_in[2];
    const float* b1  = (const float*)d_in[3];
    const float* W2  = (const float*)d_in[4];
    const float* b2  = (const float*)d_in[5];
    float* out = (float*)d_out;

    build_kernel<<<N_NODES / 8, 256>>>(adj);
    gemm1_kernel<<<dim3(N_NODES / 64, HID / 64, KSPLIT), 256>>>(x, W1);
    s1_kernel<<<S1_BLOCKS, 256>>>(b1);
    s2_kernel<<<S2_BLOCKS, 256>>>(W2, b2, out);
}